// round 10
// baseline (speedup 1.0000x reference)
#include <cuda_runtime.h>
#include <cuda_fp16.h>
#include <cstdint>

// ---------------- problem constants ----------------
#define NSAMP   131072
#define INF     8
#define NPCE    495
#define KPAD    512
#define NOUT    256
#define MTILE   128          // GEMM CTA rows
#define NTILE   128          // GEMM CTA cols (N split across 2 CTAs)
#define KC      64           // K per chunk
#define NCHUNK  (KPAD / KC)  // 8
#define NSTAGE  3

// GEMM smem: A k-major [64 k][128 m] halves, row stride 272B (17x16B granules)
#define AROWB   272
#define ABUF_BYTES (KC * AROWB)          // 17408
// B n-major [128 n][64 k] halves, row stride 144B (9x16B granules)
#define BROWB   144
#define BBUF_BYTES (NTILE * BROWB)       // 18432
#define OFF_A   0
#define OFF_B   (NSTAGE * ABUF_BYTES)    // 52224
#define GEMM_SMEM (OFF_B + NSTAGE * BBUF_BYTES)   // 107520  (x2 CTAs = 215K)

// fp16 weights, zero-padded K, [NOUT][KPAD]
__device__ __half w16g[NOUT * KPAD];
// psi staged fp16, [k][m] layout (k-major rows of 131072 halves)
__device__ __align__(16) __half psi16[(size_t)KPAD * NSAMP];

static __device__ __forceinline__ uint32_t smem_u32(const void* p) {
    uint32_t a;
    asm("{ .reg .u64 t; cvta.to.shared.u64 t, %1; cvt.u32.u64 %0, t; }" : "=r"(a) : "l"(p));
    return a;
}

// ========== fused pre-kernel: blocks 0-511 convert W, blocks 512+ gen psi ====
__global__ void __launch_bounds__(256)
pce_pre_kernel(const float* __restrict__ x, const float* __restrict__ wgt,
               const int* __restrict__ mi)
{
    const int tid = threadIdx.x;

    if (blockIdx.x < 512) {
        int idx = blockIdx.x * 256 + tid;        // 0..131071
        int n = idx >> 9, k = idx & (KPAD - 1);
        w16g[idx] = __float2half(k < NPCE ? wgt[n * NPCE + k] : 0.0f);
        return;
    }

    // ---- psi generation: one block per 128-sample tile ----
    __shared__ unsigned mi_s[KPAD];
    __shared__ float    ht[40 * MTILE];     // HT[off][m]
    const int m0 = (blockIdx.x - 512) * MTILE;

    for (int t = tid; t < KPAD; t += 256) {
        unsigned packed = 0;
        if (t < NPCE) {
            int slot = 0;
            #pragma unroll
            for (int j = 0; j < INF; j++) {
                int o = mi[t * INF + j];
                if (o > 0) { packed |= (unsigned)(j * 5 + o) << (8 * slot); slot++; }
            }
        }
        mi_s[t] = packed;
    }

    if (tid < MTILE) {
        const float4* xr = (const float4*)(x + (size_t)(m0 + tid) * INF);
        float4 xa = xr[0], xb = xr[1];
        float vx[8] = {xa.x, xa.y, xa.z, xa.w, xb.x, xb.y, xb.z, xb.w};
        #pragma unroll
        for (int j = 0; j < INF; j++) {
            float v  = vx[j];
            float h2 = v * v - 1.f;
            float h3 = v * h2 - 2.f * v;
            float h4 = v * h3 - 3.f * h2;
            ht[(j * 5 + 0) * MTILE + tid] = 1.f;
            ht[(j * 5 + 1) * MTILE + tid] = v;
            ht[(j * 5 + 2) * MTILE + tid] = h2 * 0.70710678118654752f;
            ht[(j * 5 + 3) * MTILE + tid] = h3 * 0.40824829046386302f;
            ht[(j * 5 + 4) * MTILE + tid] = h4 * 0.20412414523193151f;
        }
    }
    __syncthreads();

    // 512 k-rows x 32 m-quads; warp-uniform k, float4 lookups, 8B stores
    const float4* ht4 = (const float4*)ht;    // [off][mq], 32 float4 per row
    #pragma unroll 4
    for (int it = 0; it < 64; it++) {
        int idx = it * 256 + tid;             // 0..16383
        int k = idx >> 5, mq = idx & 31;
        unsigned p = mi_s[k];
        float4 a = ht4[(p & 255) * 32 + mq];  // p==0 -> HT row 0 = ones
        p >>= 8;
        while (p) {                           // warp-uniform slot-count skip
            float4 b = ht4[(p & 255) * 32 + mq];
            a.x *= b.x; a.y *= b.y; a.z *= b.z; a.w *= b.w;
            p >>= 8;
        }
        __half2 h01 = __floats2half2_rn(a.x, a.y);
        __half2 h23 = __floats2half2_rn(a.z, a.w);
        uint2 v = make_uint2(*(uint32_t*)&h01, *(uint32_t*)&h23);
        *(uint2*)(psi16 + (size_t)k * NSAMP + m0 + 4 * mq) = v;
    }
}

// ================= GEMM: psi16[k][m] (x) w16g[n][k] -> out[m][n] =============
static __device__ __forceinline__ void cp_async16(uint32_t dst, const void* src) {
    asm volatile("cp.async.ca.shared.global [%0], [%1], 16;" :: "r"(dst), "l"(src));
}
#define CP_COMMIT() asm volatile("cp.async.commit_group;" ::: "memory")
#define CP_WAIT1()  asm volatile("cp.async.wait_group 1;" ::: "memory")

static __device__ __forceinline__ void ldm_x4(uint32_t& r0, uint32_t& r1,
                                              uint32_t& r2, uint32_t& r3, uint32_t addr) {
    asm volatile("ldmatrix.sync.aligned.m8n8.x4.shared.b16 {%0,%1,%2,%3}, [%4];"
                 : "=r"(r0), "=r"(r1), "=r"(r2), "=r"(r3) : "r"(addr));
}
static __device__ __forceinline__ void ldm_x4_trans(uint32_t& r0, uint32_t& r1,
                                                    uint32_t& r2, uint32_t& r3, uint32_t addr) {
    asm volatile("ldmatrix.sync.aligned.m8n8.x4.trans.shared.b16 {%0,%1,%2,%3}, [%4];"
                 : "=r"(r0), "=r"(r1), "=r"(r2), "=r"(r3) : "r"(addr));
}
static __device__ __forceinline__ void mma16816(float& c0, float& c1, float& c2, float& c3,
                                                uint32_t a0, uint32_t a1, uint32_t a2, uint32_t a3,
                                                uint32_t b0, uint32_t b1) {
    asm volatile(
        "mma.sync.aligned.m16n8k16.row.col.f32.f16.f16.f32 "
        "{%0,%1,%2,%3}, {%4,%5,%6,%7}, {%8,%9}, {%0,%1,%2,%3};"
        : "+f"(c0), "+f"(c1), "+f"(c2), "+f"(c3)
        : "r"(a0), "r"(a1), "r"(a2), "r"(a3), "r"(b0), "r"(b1));
}

extern __shared__ char smem[];

__global__ void __launch_bounds__(256, 2)
pce_gemm_kernel(float* __restrict__ out)
{
    const int tid  = threadIdx.x;
    const int wid  = tid >> 5;
    const int lane = tid & 31;
    const int m0   = (blockIdx.x >> 1) * MTILE;
    const int n0   = (blockIdx.x & 1) * NTILE;

    const uint32_t sbase = smem_u32(smem);

    auto load_stage = [&](int c, int buf) {
        // A: 64 k-rows x 256B from psi16[k][m0..m0+128); 1024 granules / 256 thr
        const uint32_t adst = sbase + OFF_A + buf * ABUF_BYTES;
        #pragma unroll
        for (int j = 0; j < 4; j++) {
            int idx = tid + j * 256;             // 0..1023
            int row = idx >> 4, g = idx & 15;
            cp_async16(adst + row * AROWB + g * 16,
                       psi16 + (size_t)(c * KC + row) * NSAMP + m0 + g * 8);
        }
        // B: 128 n-rows x 128B from w16g rows n0..n0+128; 1024 granules
        const uint32_t bdst = sbase + OFF_B + buf * BBUF_BYTES;
        #pragma unroll
        for (int j = 0; j < 4; j++) {
            int idx = tid + j * 256;             // 0..1023
            int n = idx >> 3, g = idx & 7;
            cp_async16(bdst + n * BROWB + g * 16,
                       w16g + (size_t)(n0 + n) * KPAD + c * KC + g * 8);
        }
        CP_COMMIT();
    };

    // warp tiling: 4(m) x 2(n), each 32m x 64n
    const int warp_m = wid >> 1;   // 0..3
    const int warp_n = wid & 1;    // 0..1

    float acc[2][8][4];
    #pragma unroll
    for (int a = 0; a < 2; a++)
        #pragma unroll
        for (int b = 0; b < 8; b++)
            #pragma unroll
            for (int r = 0; r < 4; r++) acc[a][b][r] = 0.f;

    // prologue: fill stages 0 and 1
    load_stage(0, 0);
    load_stage(1, 1);

    const int a_row_off = (lane & 7) + ((lane >> 4) & 1) * 8;
    const int a_m_off   = ((lane >> 3) & 1) * 8;

    int buf = 0;
    for (int c = 0; c < NCHUNK; c++) {
        CP_WAIT1();            // stage c landed (<=1 groups pending)
        __syncthreads();       // all warps done reading stage c-1's buffer

        if (c + 2 < NCHUNK) {
            int nbuf = buf + 2; if (nbuf >= NSTAGE) nbuf -= NSTAGE;
            load_stage(c + 2, nbuf);   // overwrites stage c-1's buffer (safe)
        }

        const uint32_t abase = sbase + OFF_A + buf * ABUF_BYTES;
        const uint32_t b_base = sbase + OFF_B + buf * BBUF_BYTES
                              + (warp_n * 64 + ((lane >> 4) * 8) + (lane & 7)) * BROWB
                              + ((lane >> 3) & 1) * 16;

        #pragma unroll
        for (int kb = 0; kb < 4; kb++) {     // four k16 blocks per chunk
            uint32_t af[2][4], bf[4][4];
            #pragma unroll
            for (int mb = 0; mb < 2; mb++)
                ldm_x4_trans(af[mb][0], af[mb][1], af[mb][2], af[mb][3],
                             abase + (kb * 16 + a_row_off) * AROWB
                                   + (warp_m * 32 + mb * 16 + a_m_off) * 2);
            #pragma unroll
            for (int np = 0; np < 4; np++)
                ldm_x4(bf[np][0], bf[np][1], bf[np][2], bf[np][3],
                       b_base + np * 16 * BROWB + kb * 32);
            #pragma unroll
            for (int mb = 0; mb < 2; mb++)
                #pragma unroll
                for (int nb = 0; nb < 8; nb++)
                    mma16816(acc[mb][nb][0], acc[mb][nb][1], acc[mb][nb][2], acc[mb][nb][3],
                             af[mb][0], af[mb][1], af[mb][2], af[mb][3],
                             bf[nb >> 1][(nb & 1) * 2], bf[nb >> 1][(nb & 1) * 2 + 1]);
        }

        if (++buf >= NSTAGE) buf = 0;
    }

    // epilogue: direct fp32 stores
    {
        const int mw = m0 + warp_m * 32;
        const int nw = n0 + warp_n * 64;
        const int rq = lane >> 2;
        const int cq = 2 * (lane & 3);
        #pragma unroll
        for (int mb = 0; mb < 2; mb++) {
            #pragma unroll
            for (int nb = 0; nb < 8; nb++) {
                const int row = mw + mb * 16 + rq;
                const int col = nw + nb * 8 + cq;
                *(float2*)(out + (size_t)row * NOUT + col)
                    = make_float2(acc[mb][nb][0], acc[mb][nb][1]);
                *(float2*)(out + (size_t)(row + 8) * NOUT + col)
                    = make_float2(acc[mb][nb][2], acc[mb][nb][3]);
            }
        }
    }
}

extern "C" void kernel_launch(void* const* d_in, const int* in_sizes, int n_in,
                              void* d_out, int out_size) {
    const float* x   = (const float*)d_in[0];
    const float* wgt = (const float*)d_in[1];
    const int*   mi  = (const int*)d_in[2];
    float* out = (float*)d_out;

    pce_pre_kernel<<<512 + NSAMP / MTILE, 256>>>(x, wgt, mi);

    cudaFuncSetAttribute(pce_gemm_kernel,
                         cudaFuncAttributeMaxDynamicSharedMemorySize, GEMM_SMEM);
    pce_gemm_kernel<<<(NSAMP / MTILE) * (NOUT / NTILE), 256, GEMM_SMEM>>>(out);
}

// round 11
// speedup vs baseline: 1.0389x; 1.0389x over previous
#include <cuda_runtime.h>
#include <cuda_fp16.h>
#include <cstdint>

// ---------------- problem constants ----------------
#define NSAMP   131072
#define INF     8
#define NPCE    495
#define KPAD    512
#define NOUT    256
#define MTILE   128          // GEMM CTA rows
#define KC      128          // K per chunk
#define NCHUNK  (KPAD / KC)  // 4
#define NSTAGE  2

// A k-major [128 k][128 m] halves, row stride 272B (17x16B granules)
#define AROWB   272
#define ABUF_BYTES (KC * AROWB)          // 34816
// B n-major [256 n][128 k] halves, row stride 272B
#define BROWB   272
#define BBUF_BYTES (NOUT * BROWB)        // 69632
#define OFF_A   0
#define OFF_B   (NSTAGE * ABUF_BYTES)    // 69632
#define GEMM_SMEM (OFF_B + NSTAGE * BBUF_BYTES)   // 208896

// fp16 weights, zero-padded K, [NOUT][KPAD]
__device__ __half w16g[NOUT * KPAD];
// psi staged fp16, [k][m] layout (k-major rows of 131072 halves)
__device__ __align__(16) __half psi16[(size_t)KPAD * NSAMP];

static __device__ __forceinline__ uint32_t smem_u32(const void* p) {
    uint32_t a;
    asm("{ .reg .u64 t; cvta.to.shared.u64 t, %1; cvt.u32.u64 %0, t; }" : "=r"(a) : "l"(p));
    return a;
}

// ========== fused pre-kernel: blocks 0-511 convert W, blocks 512+ gen psi ====
__global__ void __launch_bounds__(256)
pce_pre_kernel(const float* __restrict__ x, const float* __restrict__ wgt,
               const int* __restrict__ mi)
{
    const int tid = threadIdx.x;

    if (blockIdx.x < 512) {
        int idx = blockIdx.x * 256 + tid;        // 0..131071
        int n = idx >> 9, k = idx & (KPAD - 1);
        w16g[idx] = __float2half(k < NPCE ? wgt[n * NPCE + k] : 0.0f);
        return;
    }

    // ---- psi generation: one block per 128-sample tile ----
    __shared__ unsigned mi_s[KPAD];
    __shared__ float    ht[40 * MTILE];     // HT[off][m]
    const int m0 = (blockIdx.x - 512) * MTILE;

    for (int t = tid; t < KPAD; t += 256) {
        unsigned packed = 0;
        if (t < NPCE) {
            int slot = 0;
            #pragma unroll
            for (int j = 0; j < INF; j++) {
                int o = mi[t * INF + j];
                if (o > 0) { packed |= (unsigned)(j * 5 + o) << (8 * slot); slot++; }
            }
        }
        mi_s[t] = packed;
    }

    if (tid < MTILE) {
        const float4* xr = (const float4*)(x + (size_t)(m0 + tid) * INF);
        float4 xa = xr[0], xb = xr[1];
        float vx[8] = {xa.x, xa.y, xa.z, xa.w, xb.x, xb.y, xb.z, xb.w};
        #pragma unroll
        for (int j = 0; j < INF; j++) {
            float v  = vx[j];
            float h2 = v * v - 1.f;
            float h3 = v * h2 - 2.f * v;
            float h4 = v * h3 - 3.f * h2;
            ht[(j * 5 + 0) * MTILE + tid] = 1.f;
            ht[(j * 5 + 1) * MTILE + tid] = v;
            ht[(j * 5 + 2) * MTILE + tid] = h2 * 0.70710678118654752f;
            ht[(j * 5 + 3) * MTILE + tid] = h3 * 0.40824829046386302f;
            ht[(j * 5 + 4) * MTILE + tid] = h4 * 0.20412414523193151f;
        }
    }
    __syncthreads();

    // 512 k-rows x 32 m-quads; warp-uniform k, float4 lookups, 8B stores
    const float4* ht4 = (const float4*)ht;    // [off][mq], 32 float4 per row
    #pragma unroll 4
    for (int it = 0; it < 64; it++) {
        int idx = it * 256 + tid;             // 0..16383
        int k = idx >> 5, mq = idx & 31;
        unsigned p = mi_s[k];
        float4 a = ht4[(p & 255) * 32 + mq];  // p==0 -> HT row 0 = ones
        p >>= 8;
        while (p) {                           // warp-uniform slot-count skip
            float4 b = ht4[(p & 255) * 32 + mq];
            a.x *= b.x; a.y *= b.y; a.z *= b.z; a.w *= b.w;
            p >>= 8;
        }
        __half2 h01 = __floats2half2_rn(a.x, a.y);
        __half2 h23 = __floats2half2_rn(a.z, a.w);
        uint2 v = make_uint2(*(uint32_t*)&h01, *(uint32_t*)&h23);
        *(uint2*)(psi16 + (size_t)k * NSAMP + m0 + 4 * mq) = v;
    }
}

// ================= GEMM: psi16[k][m] (x) w16g[n][k] -> out[m][n] =============
static __device__ __forceinline__ void cp_async16(uint32_t dst, const void* src) {
    asm volatile("cp.async.ca.shared.global [%0], [%1], 16;" :: "r"(dst), "l"(src));
}
#define CP_COMMIT() asm volatile("cp.async.commit_group;" ::: "memory")
#define CP_WAIT0()  asm volatile("cp.async.wait_group 0;" ::: "memory")

static __device__ __forceinline__ void ldm_x4(uint32_t& r0, uint32_t& r1,
                                              uint32_t& r2, uint32_t& r3, uint32_t addr) {
    asm volatile("ldmatrix.sync.aligned.m8n8.x4.shared.b16 {%0,%1,%2,%3}, [%4];"
                 : "=r"(r0), "=r"(r1), "=r"(r2), "=r"(r3) : "r"(addr));
}
static __device__ __forceinline__ void ldm_x4_trans(uint32_t& r0, uint32_t& r1,
                                                    uint32_t& r2, uint32_t& r3, uint32_t addr) {
    asm volatile("ldmatrix.sync.aligned.m8n8.x4.trans.shared.b16 {%0,%1,%2,%3}, [%4];"
                 : "=r"(r0), "=r"(r1), "=r"(r2), "=r"(r3) : "r"(addr));
}
static __device__ __forceinline__ void mma16816(float& c0, float& c1, float& c2, float& c3,
                                                uint32_t a0, uint32_t a1, uint32_t a2, uint32_t a3,
                                                uint32_t b0, uint32_t b1) {
    asm volatile(
        "mma.sync.aligned.m16n8k16.row.col.f32.f16.f16.f32 "
        "{%0,%1,%2,%3}, {%4,%5,%6,%7}, {%8,%9}, {%0,%1,%2,%3};"
        : "+f"(c0), "+f"(c1), "+f"(c2), "+f"(c3)
        : "r"(a0), "r"(a1), "r"(a2), "r"(a3), "r"(b0), "r"(b1));
}

extern __shared__ char smem[];

__global__ void __launch_bounds__(512, 1)
pce_gemm_kernel(float* __restrict__ out)
{
    const int tid  = threadIdx.x;
    const int wid  = tid >> 5;
    const int lane = tid & 31;
    const int m0   = blockIdx.x * MTILE;

    const uint32_t sbase = smem_u32(smem);

    auto load_stage = [&](int c, int buf) {
        // A: 128 k-rows x 256B from psi16[k][m0..m0+128); 2048 granules / 512 thr
        const uint32_t adst = sbase + OFF_A + buf * ABUF_BYTES;
        #pragma unroll
        for (int j = 0; j < 4; j++) {
            int idx = tid + j * 512;             // 0..2047
            int row = idx >> 4, g = idx & 15;
            cp_async16(adst + row * AROWB + g * 16,
                       psi16 + (size_t)(c * KC + row) * NSAMP + m0 + g * 8);
        }
        // B: 256 n-rows x 256B from w16g; 4096 granules / 512 thr
        const uint32_t bdst = sbase + OFF_B + buf * BBUF_BYTES;
        #pragma unroll
        for (int j = 0; j < 8; j++) {
            int idx = tid + j * 512;             // 0..4095
            int n = idx >> 4, g = idx & 15;
            cp_async16(bdst + n * BROWB + g * 16,
                       w16g + (size_t)n * KPAD + c * KC + g * 8);
        }
        CP_COMMIT();
    };

    // warp tiling: 4(m) x 4(n), each 32m x 64n
    const int warp_m = wid >> 2;   // 0..3
    const int warp_n = wid & 3;    // 0..3

    float acc[2][8][4];
    #pragma unroll
    for (int a = 0; a < 2; a++)
        #pragma unroll
        for (int b = 0; b < 8; b++)
            #pragma unroll
            for (int r = 0; r < 4; r++) acc[a][b][r] = 0.f;

    load_stage(0, 0);   // prologue: stage 0 only (2-stage, wait0 discipline)

    const int a_row_off = (lane & 7) + ((lane >> 4) & 1) * 8;
    const int a_m_off   = ((lane >> 3) & 1) * 8;

    for (int c = 0; c < NCHUNK; c++) {
        const int cb = c & 1;
        CP_WAIT0();            // stage c landed
        __syncthreads();       // + all warps finished reading buffer cb (chunk c-2)

        if (c + 1 < NCHUNK)
            load_stage(c + 1, cb ^ 1);   // buffer cb^1 free: consumed in chunk c-1

        const uint32_t abase = sbase + OFF_A + cb * ABUF_BYTES;
        const uint32_t b_base = sbase + OFF_B + cb * BBUF_BYTES
                              + (warp_n * 64 + ((lane >> 4) * 8) + (lane & 7)) * BROWB
                              + ((lane >> 3) & 1) * 16;

        #pragma unroll
        for (int kb = 0; kb < 8; kb++) {     // eight k16 blocks per chunk
            uint32_t af[2][4], bf[4][4];
            #pragma unroll
            for (int mb = 0; mb < 2; mb++)
                ldm_x4_trans(af[mb][0], af[mb][1], af[mb][2], af[mb][3],
                             abase + (kb * 16 + a_row_off) * AROWB
                                   + (warp_m * 32 + mb * 16 + a_m_off) * 2);
            #pragma unroll
            for (int np = 0; np < 4; np++)
                ldm_x4(bf[np][0], bf[np][1], bf[np][2], bf[np][3],
                       b_base + np * 16 * BROWB + kb * 32);
            #pragma unroll
            for (int mb = 0; mb < 2; mb++)
                #pragma unroll
                for (int nb = 0; nb < 8; nb++)
                    mma16816(acc[mb][nb][0], acc[mb][nb][1], acc[mb][nb][2], acc[mb][nb][3],
                             af[mb][0], af[mb][1], af[mb][2], af[mb][3],
                             bf[nb >> 1][(nb & 1) * 2], bf[nb >> 1][(nb & 1) * 2 + 1]);
        }
    }

    // epilogue: direct fp32 stores
    {
        const int mw = m0 + warp_m * 32;
        const int nw = warp_n * 64;
        const int rq = lane >> 2;
        const int cq = 2 * (lane & 3);
        #pragma unroll
        for (int mb = 0; mb < 2; mb++) {
            #pragma unroll
            for (int nb = 0; nb < 8; nb++) {
                const int row = mw + mb * 16 + rq;
                const int col = nw + nb * 8 + cq;
                *(float2*)(out + (size_t)row * NOUT + col)
                    = make_float2(acc[mb][nb][0], acc[mb][nb][1]);
                *(float2*)(out + (size_t)(row + 8) * NOUT + col)
                    = make_float2(acc[mb][nb][2], acc[mb][nb][3]);
            }
        }
    }
}

extern "C" void kernel_launch(void* const* d_in, const int* in_sizes, int n_in,
                              void* d_out, int out_size) {
    const float* x   = (const float*)d_in[0];
    const float* wgt = (const float*)d_in[1];
    const int*   mi  = (const int*)d_in[2];
    float* out = (float*)d_out;

    pce_pre_kernel<<<512 + NSAMP / MTILE, 256>>>(x, wgt, mi);

    cudaFuncSetAttribute(pce_gemm_kernel,
                         cudaFuncAttributeMaxDynamicSharedMemorySize, GEMM_SMEM);
    pce_gemm_kernel<<<NSAMP / MTILE, 512, GEMM_SMEM>>>(out);
}

// round 12
// speedup vs baseline: 1.1543x; 1.1111x over previous
#include <cuda_runtime.h>
#include <cuda_fp16.h>
#include <cstdint>

// ---------------- problem constants ----------------
#define NSAMP   131072
#define INF     8
#define NPCE    495
#define KPAD    512
#define NOUT    256
#define MTILE   128          // GEMM CTA rows
#define KC      64           // K per chunk (R9-validated optimum)
#define NCHUNK  (KPAD / KC)  // 8
#define NSTAGE  4

// A k-major [64 k][128 m] halves, row stride 272B (17x16B granules)
#define AROWB   272
#define ABUF_BYTES (KC * AROWB)          // 17408
// B n-major [256 n][64 k] halves, row stride 144B (9x16B granules)
#define BROWB   144
#define BBUF_BYTES (NOUT * BROWB)        // 36864
#define OFF_A   0
#define OFF_B   (NSTAGE * ABUF_BYTES)    // 69632
#define GEMM_SMEM (OFF_B + NSTAGE * BBUF_BYTES)   // 217088

// fp16 weights, zero-padded K, [NOUT][KPAD]
__device__ __half w16g[NOUT * KPAD];
// psi staged fp16, [k][m] layout (k-major rows of 131072 halves)
__device__ __align__(16) __half psi16[(size_t)KPAD * NSAMP];

static __device__ __forceinline__ uint32_t smem_u32(const void* p) {
    uint32_t a;
    asm("{ .reg .u64 t; cvta.to.shared.u64 t, %1; cvt.u32.u64 %0, t; }" : "=r"(a) : "l"(p));
    return a;
}

// ========== fused pre-kernel: blocks 0-511 convert W, blocks 512+ gen psi ====
__global__ void __launch_bounds__(256)
pce_pre_kernel(const float* __restrict__ x, const float* __restrict__ wgt,
               const int* __restrict__ mi)
{
    const int tid = threadIdx.x;

    if (blockIdx.x < 512) {
        int idx = blockIdx.x * 256 + tid;        // 0..131071
        int n = idx >> 9, k = idx & (KPAD - 1);
        w16g[idx] = __float2half(k < NPCE ? wgt[n * NPCE + k] : 0.0f);
        return;
    }

    // ---- psi generation: one block per 128-sample tile ----
    __shared__ unsigned mi_s[KPAD];
    __shared__ float    ht[40 * MTILE];     // HT[off][m]
    const int m0 = (blockIdx.x - 512) * MTILE;

    for (int t = tid; t < KPAD; t += 256) {
        unsigned packed = 0;
        if (t < NPCE) {
            int slot = 0;
            #pragma unroll
            for (int j = 0; j < INF; j++) {
                int o = mi[t * INF + j];
                if (o > 0) { packed |= (unsigned)(j * 5 + o) << (8 * slot); slot++; }
            }
        }
        mi_s[t] = packed;
    }

    if (tid < MTILE) {
        const float4* xr = (const float4*)(x + (size_t)(m0 + tid) * INF);
        float4 xa = xr[0], xb = xr[1];
        float vx[8] = {xa.x, xa.y, xa.z, xa.w, xb.x, xb.y, xb.z, xb.w};
        #pragma unroll
        for (int j = 0; j < INF; j++) {
            float v  = vx[j];
            float h2 = v * v - 1.f;
            float h3 = v * h2 - 2.f * v;
            float h4 = v * h3 - 3.f * h2;
            ht[(j * 5 + 0) * MTILE + tid] = 1.f;
            ht[(j * 5 + 1) * MTILE + tid] = v;
            ht[(j * 5 + 2) * MTILE + tid] = h2 * 0.70710678118654752f;
            ht[(j * 5 + 3) * MTILE + tid] = h3 * 0.40824829046386302f;
            ht[(j * 5 + 4) * MTILE + tid] = h4 * 0.20412414523193151f;
        }
    }
    __syncthreads();

    // 512 k-rows x 32 m-quads; warp-uniform k, float4 lookups, 8B stores
    const float4* ht4 = (const float4*)ht;    // [off][mq], 32 float4 per row
    #pragma unroll 4
    for (int it = 0; it < 64; it++) {
        int idx = it * 256 + tid;             // 0..16383
        int k = idx >> 5, mq = idx & 31;
        unsigned p = mi_s[k];
        float4 a = ht4[(p & 255) * 32 + mq];  // p==0 -> HT row 0 = ones
        p >>= 8;
        while (p) {                           // warp-uniform slot-count skip
            float4 b = ht4[(p & 255) * 32 + mq];
            a.x *= b.x; a.y *= b.y; a.z *= b.z; a.w *= b.w;
            p >>= 8;
        }
        __half2 h01 = __floats2half2_rn(a.x, a.y);
        __half2 h23 = __floats2half2_rn(a.z, a.w);
        uint2 v = make_uint2(*(uint32_t*)&h01, *(uint32_t*)&h23);
        *(uint2*)(psi16 + (size_t)k * NSAMP + m0 + 4 * mq) = v;
    }
}

// ================= GEMM: psi16[k][m] (x) w16g[n][k] -> out[m][n] =============
static __device__ __forceinline__ void cp_async16(uint32_t dst, const void* src) {
    asm volatile("cp.async.cg.shared.global [%0], [%1], 16;" :: "r"(dst), "l"(src));
}
#define CP_COMMIT() asm volatile("cp.async.commit_group;" ::: "memory")
#define CP_WAIT2()  asm volatile("cp.async.wait_group 2;" ::: "memory")

static __device__ __forceinline__ void ldm_x4(uint32_t& r0, uint32_t& r1,
                                              uint32_t& r2, uint32_t& r3, uint32_t addr) {
    asm volatile("ldmatrix.sync.aligned.m8n8.x4.shared.b16 {%0,%1,%2,%3}, [%4];"
                 : "=r"(r0), "=r"(r1), "=r"(r2), "=r"(r3) : "r"(addr));
}
static __device__ __forceinline__ void ldm_x4_trans(uint32_t& r0, uint32_t& r1,
                                                    uint32_t& r2, uint32_t& r3, uint32_t addr) {
    asm volatile("ldmatrix.sync.aligned.m8n8.x4.trans.shared.b16 {%0,%1,%2,%3}, [%4];"
                 : "=r"(r0), "=r"(r1), "=r"(r2), "=r"(r3) : "r"(addr));
}
static __device__ __forceinline__ void mma16816(float& c0, float& c1, float& c2, float& c3,
                                                uint32_t a0, uint32_t a1, uint32_t a2, uint32_t a3,
                                                uint32_t b0, uint32_t b1) {
    asm volatile(
        "mma.sync.aligned.m16n8k16.row.col.f32.f16.f16.f32 "
        "{%0,%1,%2,%3}, {%4,%5,%6,%7}, {%8,%9}, {%0,%1,%2,%3};"
        : "+f"(c0), "+f"(c1), "+f"(c2), "+f"(c3)
        : "r"(a0), "r"(a1), "r"(a2), "r"(a3), "r"(b0), "r"(b1));
}

extern __shared__ char smem[];

__global__ void __launch_bounds__(512, 1)
pce_gemm_kernel(float* __restrict__ out)
{
    const int tid  = threadIdx.x;
    const int wid  = tid >> 5;
    const int lane = tid & 31;
    const int m0   = blockIdx.x * MTILE;

    const uint32_t sbase = smem_u32(smem);

    auto load_stage = [&](int c, int buf) {
        // A: 64 k-rows x 256B from psi16[k][m0..m0+128); 1024 granules / 512 thr
        const uint32_t adst = sbase + OFF_A + buf * ABUF_BYTES;
        #pragma unroll
        for (int j = 0; j < 2; j++) {
            int idx = tid + j * 512;             // 0..1023
            int row = idx >> 4, g = idx & 15;
            cp_async16(adst + row * AROWB + g * 16,
                       psi16 + (size_t)(c * KC + row) * NSAMP + m0 + g * 8);
        }
        // B: 256 n-rows x 128B from w16g; 2048 granules / 512 thr
        const uint32_t bdst = sbase + OFF_B + buf * BBUF_BYTES;
        #pragma unroll
        for (int j = 0; j < 4; j++) {
            int idx = tid + j * 512;             // 0..2047
            int n = idx >> 3, g = idx & 7;
            cp_async16(bdst + n * BROWB + g * 16,
                       w16g + (size_t)n * KPAD + c * KC + g * 8);
        }
        CP_COMMIT();
    };

    // warp tiling: 4(m) x 4(n), each 32m x 64n
    const int warp_m = wid >> 2;   // 0..3
    const int warp_n = wid & 3;    // 0..3

    float acc[2][8][4];
    #pragma unroll
    for (int a = 0; a < 2; a++)
        #pragma unroll
        for (int b = 0; b < 8; b++)
            #pragma unroll
            for (int r = 0; r < 4; r++) acc[a][b][r] = 0.f;

    // prologue: fill stages 0..2
    load_stage(0, 0);
    load_stage(1, 1);
    load_stage(2, 2);

    const int a_row_off = (lane & 7) + ((lane >> 4) & 1) * 8;
    const int a_m_off   = ((lane >> 3) & 1) * 8;

    int buf = 0;
    for (int c = 0; c < NCHUNK; c++) {
        CP_WAIT2();            // stage c landed (<=2 groups pending)
        __syncthreads();       // all warps done reading buffer of chunk c-1

        if (c + 3 < NCHUNK) {
            int nbuf = buf + 3; if (nbuf >= NSTAGE) nbuf -= NSTAGE;
            load_stage(c + 3, nbuf);   // overwrites stage c-1's buffer (safe)
        }

        const uint32_t abase = sbase + OFF_A + buf * ABUF_BYTES;
        const uint32_t b_base = sbase + OFF_B + buf * BBUF_BYTES
                              + (warp_n * 64 + ((lane >> 4) * 8) + (lane & 7)) * BROWB
                              + ((lane >> 3) & 1) * 16;

        #pragma unroll
        for (int kb = 0; kb < 4; kb++) {     // four k16 blocks per chunk
            uint32_t af[2][4], bf[4][4];
            #pragma unroll
            for (int mb = 0; mb < 2; mb++)
                ldm_x4_trans(af[mb][0], af[mb][1], af[mb][2], af[mb][3],
                             abase + (kb * 16 + a_row_off) * AROWB
                                   + (warp_m * 32 + mb * 16 + a_m_off) * 2);
            #pragma unroll
            for (int np = 0; np < 4; np++)
                ldm_x4(bf[np][0], bf[np][1], bf[np][2], bf[np][3],
                       b_base + np * 16 * BROWB + kb * 32);
            #pragma unroll
            for (int mb = 0; mb < 2; mb++)
                #pragma unroll
                for (int nb = 0; nb < 8; nb++)
                    mma16816(acc[mb][nb][0], acc[mb][nb][1], acc[mb][nb][2], acc[mb][nb][3],
                             af[mb][0], af[mb][1], af[mb][2], af[mb][3],
                             bf[nb >> 1][(nb & 1) * 2], bf[nb >> 1][(nb & 1) * 2 + 1]);
        }

        if (++buf >= NSTAGE) buf = 0;
    }

    // epilogue: direct fp32 stores
    {
        const int mw = m0 + warp_m * 32;
        const int nw = warp_n * 64;
        const int rq = lane >> 2;
        const int cq = 2 * (lane & 3);
        #pragma unroll
        for (int mb = 0; mb < 2; mb++) {
            #pragma unroll
            for (int nb = 0; nb < 8; nb++) {
                const int row = mw + mb * 16 + rq;
                const int col = nw + nb * 8 + cq;
                *(float2*)(out + (size_t)row * NOUT + col)
                    = make_float2(acc[mb][nb][0], acc[mb][nb][1]);
                *(float2*)(out + (size_t)(row + 8) * NOUT + col)
                    = make_float2(acc[mb][nb][2], acc[mb][nb][3]);
            }
        }
    }
}

extern "C" void kernel_launch(void* const* d_in, const int* in_sizes, int n_in,
                              void* d_out, int out_size) {
    const float* x   = (const float*)d_in[0];
    const float* wgt = (const float*)d_in[1];
    const int*   mi  = (const int*)d_in[2];
    float* out = (float*)d_out;

    pce_pre_kernel<<<512 + NSAMP / MTILE, 256>>>(x, wgt, mi);

    cudaFuncSetAttribute(pce_gemm_kernel,
                         cudaFuncAttributeMaxDynamicSharedMemorySize, GEMM_SMEM);
    pce_gemm_kernel<<<NSAMP / MTILE, 512, GEMM_SMEM>>>(out);
}

// round 13
// speedup vs baseline: 1.1731x; 1.0162x over previous
#include <cuda_runtime.h>
#include <cuda_fp16.h>
#include <cstdint>

// ---------------- problem constants ----------------
#define NSAMP   131072
#define INF     8
#define NPCE    495
#define KPAD    512
#define NOUT    256
#define PTILE   128          // pre-kernel psi tile rows
#define MTILE   64           // GEMM CTA rows (M-split for 2 CTAs/SM)
#define KC      64           // K per chunk
#define NCHUNK  (KPAD / KC)  // 8
#define NSTAGE  2

// A k-major [64 k][64 m] halves, row stride 144B (9x16B granules)
#define AROWB   144
#define ABUF_BYTES (KC * AROWB)          // 9216
// B n-major [256 n][64 k] halves, row stride 144B
#define BROWB   144
#define BBUF_BYTES (NOUT * BROWB)        // 36864
#define OFF_A   0
#define OFF_B   (NSTAGE * ABUF_BYTES)    // 18432
#define GEMM_SMEM (OFF_B + NSTAGE * BBUF_BYTES)   // 92160 (x2 CTAs = 184K)

// fp16 weights, zero-padded K, [NOUT][KPAD]
__device__ __half w16g[NOUT * KPAD];
// psi staged fp16, [k][m] layout (k-major rows of 131072 halves)
__device__ __align__(16) __half psi16[(size_t)KPAD * NSAMP];

static __device__ __forceinline__ uint32_t smem_u32(const void* p) {
    uint32_t a;
    asm("{ .reg .u64 t; cvta.to.shared.u64 t, %1; cvt.u32.u64 %0, t; }" : "=r"(a) : "l"(p));
    return a;
}

// ========== fused pre-kernel: blocks 0-511 convert W, blocks 512+ gen psi ====
__global__ void __launch_bounds__(256)
pce_pre_kernel(const float* __restrict__ x, const float* __restrict__ wgt,
               const int* __restrict__ mi)
{
    const int tid = threadIdx.x;

    if (blockIdx.x < 512) {
        int idx = blockIdx.x * 256 + tid;        // 0..131071
        int n = idx >> 9, k = idx & (KPAD - 1);
        w16g[idx] = __float2half(k < NPCE ? wgt[n * NPCE + k] : 0.0f);
        return;
    }

    // ---- psi generation: one block per 128-sample tile ----
    __shared__ unsigned mi_s[KPAD];
    __shared__ float    ht[40 * PTILE];     // HT[off][m]
    const int m0 = (blockIdx.x - 512) * PTILE;

    for (int t = tid; t < KPAD; t += 256) {
        unsigned packed = 0;
        if (t < NPCE) {
            int slot = 0;
            #pragma unroll
            for (int j = 0; j < INF; j++) {
                int o = mi[t * INF + j];
                if (o > 0) { packed |= (unsigned)(j * 5 + o) << (8 * slot); slot++; }
            }
        }
        mi_s[t] = packed;
    }

    if (tid < PTILE) {
        const float4* xr = (const float4*)(x + (size_t)(m0 + tid) * INF);
        float4 xa = xr[0], xb = xr[1];
        float vx[8] = {xa.x, xa.y, xa.z, xa.w, xb.x, xb.y, xb.z, xb.w};
        #pragma unroll
        for (int j = 0; j < INF; j++) {
            float v  = vx[j];
            float h2 = v * v - 1.f;
            float h3 = v * h2 - 2.f * v;
            float h4 = v * h3 - 3.f * h2;
            ht[(j * 5 + 0) * PTILE + tid] = 1.f;
            ht[(j * 5 + 1) * PTILE + tid] = v;
            ht[(j * 5 + 2) * PTILE + tid] = h2 * 0.70710678118654752f;
            ht[(j * 5 + 3) * PTILE + tid] = h3 * 0.40824829046386302f;
            ht[(j * 5 + 4) * PTILE + tid] = h4 * 0.20412414523193151f;
        }
    }
    __syncthreads();

    // 512 k-rows x 32 m-quads; warp-uniform k, float4 lookups, 8B stores
    const float4* ht4 = (const float4*)ht;    // [off][mq], 32 float4 per row
    #pragma unroll 4
    for (int it = 0; it < 64; it++) {
        int idx = it * 256 + tid;             // 0..16383
        int k = idx >> 5, mq = idx & 31;
        unsigned p = mi_s[k];
        float4 a = ht4[(p & 255) * 32 + mq];  // p==0 -> HT row 0 = ones
        p >>= 8;
        while (p) {                           // warp-uniform slot-count skip
            float4 b = ht4[(p & 255) * 32 + mq];
            a.x *= b.x; a.y *= b.y; a.z *= b.z; a.w *= b.w;
            p >>= 8;
        }
        __half2 h01 = __floats2half2_rn(a.x, a.y);
        __half2 h23 = __floats2half2_rn(a.z, a.w);
        uint2 v = make_uint2(*(uint32_t*)&h01, *(uint32_t*)&h23);
        *(uint2*)(psi16 + (size_t)k * NSAMP + m0 + 4 * mq) = v;
    }
}

// ================= GEMM: psi16[k][m] (x) w16g[n][k] -> out[m][n] =============
static __device__ __forceinline__ void cp_async16(uint32_t dst, const void* src) {
    asm volatile("cp.async.cg.shared.global [%0], [%1], 16;" :: "r"(dst), "l"(src));
}
#define CP_COMMIT() asm volatile("cp.async.commit_group;" ::: "memory")
#define CP_WAIT0()  asm volatile("cp.async.wait_group 0;" ::: "memory")

static __device__ __forceinline__ void ldm_x4(uint32_t& r0, uint32_t& r1,
                                              uint32_t& r2, uint32_t& r3, uint32_t addr) {
    asm volatile("ldmatrix.sync.aligned.m8n8.x4.shared.b16 {%0,%1,%2,%3}, [%4];"
                 : "=r"(r0), "=r"(r1), "=r"(r2), "=r"(r3) : "r"(addr));
}
static __device__ __forceinline__ void ldm_x4_trans(uint32_t& r0, uint32_t& r1,
                                                    uint32_t& r2, uint32_t& r3, uint32_t addr) {
    asm volatile("ldmatrix.sync.aligned.m8n8.x4.trans.shared.b16 {%0,%1,%2,%3}, [%4];"
                 : "=r"(r0), "=r"(r1), "=r"(r2), "=r"(r3) : "r"(addr));
}
static __device__ __forceinline__ void mma16816(float& c0, float& c1, float& c2, float& c3,
                                                uint32_t a0, uint32_t a1, uint32_t a2, uint32_t a3,
                                                uint32_t b0, uint32_t b1) {
    asm volatile(
        "mma.sync.aligned.m16n8k16.row.col.f32.f16.f16.f32 "
        "{%0,%1,%2,%3}, {%4,%5,%6,%7}, {%8,%9}, {%0,%1,%2,%3};"
        : "+f"(c0), "+f"(c1), "+f"(c2), "+f"(c3)
        : "r"(a0), "r"(a1), "r"(a2), "r"(a3), "r"(b0), "r"(b1));
}

extern __shared__ char smem[];

__global__ void __launch_bounds__(256, 2)
pce_gemm_kernel(float* __restrict__ out)
{
    const int tid  = threadIdx.x;
    const int wid  = tid >> 5;
    const int lane = tid & 31;
    // reversed tile order: start on the psi tiles most recently written (L2-hot)
    const int m0   = (int)(gridDim.x - 1 - blockIdx.x) * MTILE;

    const uint32_t sbase = smem_u32(smem);

    auto load_stage = [&](int c, int buf) {
        // A: 64 k-rows x 128B from psi16[k][m0..m0+64); 512 granules / 256 thr
        const uint32_t adst = sbase + OFF_A + buf * ABUF_BYTES;
        #pragma unroll
        for (int j = 0; j < 2; j++) {
            int idx = tid + j * 256;             // 0..511
            int row = idx >> 3, g = idx & 7;
            cp_async16(adst + row * AROWB + g * 16,
                       psi16 + (size_t)(c * KC + row) * NSAMP + m0 + g * 8);
        }
        // B: 256 n-rows x 128B from w16g; 2048 granules / 256 thr
        const uint32_t bdst = sbase + OFF_B + buf * BBUF_BYTES;
        #pragma unroll
        for (int j = 0; j < 8; j++) {
            int idx = tid + j * 256;             // 0..2047
            int n = idx >> 3, g = idx & 7;
            cp_async16(bdst + n * BROWB + g * 16,
                       w16g + (size_t)n * KPAD + c * KC + g * 8);
        }
        CP_COMMIT();
    };

    // warp tiling: 2(m) x 4(n), each 32m x 64n (identical per-warp tile to R9)
    const int warp_m = wid >> 2;   // 0..1
    const int warp_n = wid & 3;    // 0..3

    float acc[2][8][4];
    #pragma unroll
    for (int a = 0; a < 2; a++)
        #pragma unroll
        for (int b = 0; b < 8; b++)
            #pragma unroll
            for (int r = 0; r < 4; r++) acc[a][b][r] = 0.f;

    load_stage(0, 0);   // prologue: stage 0 (2-stage; co-CTA covers fill tails)

    const int a_row_off = (lane & 7) + ((lane >> 4) & 1) * 8;
    const int a_m_off   = ((lane >> 3) & 1) * 8;

    for (int c = 0; c < NCHUNK; c++) {
        const int cb = c & 1;
        CP_WAIT0();            // stage c landed
        __syncthreads();       // all warps finished reading buffer cb^1 (chunk c-1)

        if (c + 1 < NCHUNK)
            load_stage(c + 1, cb ^ 1);

        const uint32_t abase = sbase + OFF_A + cb * ABUF_BYTES;
        const uint32_t b_base = sbase + OFF_B + cb * BBUF_BYTES
                              + (warp_n * 64 + ((lane >> 4) * 8) + (lane & 7)) * BROWB
                              + ((lane >> 3) & 1) * 16;

        #pragma unroll
        for (int kb = 0; kb < 4; kb++) {     // four k16 blocks per chunk
            uint32_t af[2][4], bf[4][4];
            #pragma unroll
            for (int mb = 0; mb < 2; mb++)
                ldm_x4_trans(af[mb][0], af[mb][1], af[mb][2], af[mb][3],
                             abase + (kb * 16 + a_row_off) * AROWB
                                   + (warp_m * 32 + mb * 16 + a_m_off) * 2);
            #pragma unroll
            for (int np = 0; np < 4; np++)
                ldm_x4(bf[np][0], bf[np][1], bf[np][2], bf[np][3],
                       b_base + np * 16 * BROWB + kb * 32);
            #pragma unroll
            for (int mb = 0; mb < 2; mb++)
                #pragma unroll
                for (int nb = 0; nb < 8; nb++)
                    mma16816(acc[mb][nb][0], acc[mb][nb][1], acc[mb][nb][2], acc[mb][nb][3],
                             af[mb][0], af[mb][1], af[mb][2], af[mb][3],
                             bf[nb >> 1][(nb & 1) * 2], bf[nb >> 1][(nb & 1) * 2 + 1]);
        }
    }

    // epilogue: direct fp32 stores
    {
        const int mw = m0 + warp_m * 32;
        const int nw = warp_n * 64;
        const int rq = lane >> 2;
        const int cq = 2 * (lane & 3);
        #pragma unroll
        for (int mb = 0; mb < 2; mb++) {
            #pragma unroll
            for (int nb = 0; nb < 8; nb++) {
                const int row = mw + mb * 16 + rq;
                const int col = nw + nb * 8 + cq;
                *(float2*)(out + (size_t)row * NOUT + col)
                    = make_float2(acc[mb][nb][0], acc[mb][nb][1]);
                *(float2*)(out + (size_t)(row + 8) * NOUT + col)
                    = make_float2(acc[mb][nb][2], acc[mb][nb][3]);
            }
        }
    }
}

extern "C" void kernel_launch(void* const* d_in, const int* in_sizes, int n_in,
                              void* d_out, int out_size) {
    const float* x   = (const float*)d_in[0];
    const float* wgt = (const float*)d_in[1];
    const int*   mi  = (const int*)d_in[2];
    float* out = (float*)d_out;

    pce_pre_kernel<<<512 + NSAMP / PTILE, 256>>>(x, wgt, mi);

    cudaFuncSetAttribute(pce_gemm_kernel,
                         cudaFuncAttributeMaxDynamicSharedMemorySize, GEMM_SMEM);
    pce_gemm_kernel<<<NSAMP / MTILE, 256, GEMM_SMEM>>>(out);
}